// round 1
// baseline (speedup 1.0000x reference)
#include <cuda_runtime.h>

#define NN   50000
#define EE   800000
#define FIN  256
#define FOUT 96
#define NF   3
#define FT   (NF * FOUT)   // 288
#define EPS  0.1f

// Scratch (allocation-free rule: __device__ globals)
__device__ __align__(128) float g_T[(size_t)NN * FT];          // 57.6 MB: D_f * (x @ W_f), filter-major cols
__device__ __align__(128) float g_ACC[(size_t)NF * NN * FOUT]; // 57.6 MB: accumulators
__device__ float g_deg[NN];

// ---------------------------------------------------------------------------
// degree = 1 + count of edges per row
// ---------------------------------------------------------------------------
__global__ void k_deg_init() {
    int i = blockIdx.x * blockDim.x + threadIdx.x;
    if (i < NN) g_deg[i] = 1.0f;
}

__global__ void k_deg_acc(const int* __restrict__ ei) {
    int e = blockIdx.x * blockDim.x + threadIdx.x;
    if (e < EE) atomicAdd(&g_deg[ei[e]], 1.0f);  // ei[0..E) = row
}

// ---------------------------------------------------------------------------
// T[n][f*96+c] = ds[f][n] * sum_k x[n][k] * W[f][k][c]
// Tiled SGEMM: BM=128, BN=96 (one filter per blockIdx.y), BK=16, 256 threads,
// 8x6 per-thread microtile.
// ---------------------------------------------------------------------------
__global__ __launch_bounds__(256) void k_gemm(const float* __restrict__ x,
                                              const float* __restrict__ w,
                                              const float* __restrict__ ds) {
    __shared__ float As[16][128];
    __shared__ float Bs[16][96];

    const int m0 = blockIdx.x * 128;
    const int f  = blockIdx.y;
    const float* W = w + (size_t)f * FIN * FOUT;

    const int tid = threadIdx.x;
    const int tr = tid >> 4;   // 0..15
    const int tc = tid & 15;   // 0..15

    float acc[8][6];
    #pragma unroll
    for (int i = 0; i < 8; i++)
        #pragma unroll
        for (int j = 0; j < 6; j++) acc[i][j] = 0.0f;

    for (int k0 = 0; k0 < FIN; k0 += 16) {
        // Load A tile: 128 rows x 16 k = 512 float4, 2 per thread
        #pragma unroll
        for (int i = 0; i < 2; i++) {
            int idx = tid + i * 256;       // float4 index 0..511
            int mm  = idx >> 2;            // row in tile
            int kk  = (idx & 3) << 2;      // k offset 0,4,8,12
            int gm  = m0 + mm;
            float4 v = make_float4(0.f, 0.f, 0.f, 0.f);
            if (gm < NN)
                v = *(const float4*)(x + (size_t)gm * FIN + k0 + kk);
            As[kk + 0][mm] = v.x;
            As[kk + 1][mm] = v.y;
            As[kk + 2][mm] = v.z;
            As[kk + 3][mm] = v.w;
        }
        // Load B tile: 16 x 96 = 1536 floats, 6 per thread
        #pragma unroll
        for (int i = 0; i < 6; i++) {
            int idx = tid + i * 256;
            int kk  = idx / 96;
            int cc  = idx - kk * 96;
            Bs[kk][cc] = W[(size_t)(k0 + kk) * FOUT + cc];
        }
        __syncthreads();

        #pragma unroll
        for (int kk = 0; kk < 16; kk++) {
            float a[8], b[6];
            #pragma unroll
            for (int i = 0; i < 8; i++) a[i] = As[kk][tr * 8 + i];
            #pragma unroll
            for (int j = 0; j < 6; j++) b[j] = Bs[kk][tc * 6 + j];
            #pragma unroll
            for (int i = 0; i < 8; i++)
                #pragma unroll
                for (int j = 0; j < 6; j++)
                    acc[i][j] = fmaf(a[i], b[j], acc[i][j]);
        }
        __syncthreads();
    }

    // Epilogue: scale by d_scales[f][row] and store to g_T
    #pragma unroll
    for (int i = 0; i < 8; i++) {
        int gm = m0 + tr * 8 + i;
        if (gm < NN) {
            float s = ds[(size_t)f * NN + gm];
            #pragma unroll
            for (int j = 0; j < 6; j++)
                g_T[(size_t)gm * FT + f * FOUT + tc * 6 + j] = s * acc[i][j];
        }
    }
}

// ---------------------------------------------------------------------------
// ACC[f][n][c] = sign_f * (EPS / deg[n]) * T[n][f*96+c]
// (folds the diagonal term into the accumulator init — replaces a memset)
// ---------------------------------------------------------------------------
__global__ void k_acc_init() {
    int n = blockIdx.x;
    int f = blockIdx.y;
    int c = threadIdx.x;
    float sign  = (f == 0) ? -1.0f : 1.0f;
    float scale = sign * EPS / g_deg[n];
    g_ACC[((size_t)f * NN + n) * FOUT + c] =
        scale * g_T[(size_t)n * FT + f * FOUT + c];
}

// ---------------------------------------------------------------------------
// SPMM: for each (edge, filter): ACC[f][row] += adj[e] * T[col][f*96 : f*96+96]
// One warp per (edge, filter); 24 active lanes x float4; vectorized red.
// ---------------------------------------------------------------------------
__global__ __launch_bounds__(256) void k_spmm(const int* __restrict__ ei,
                                              const float* __restrict__ adj) {
    int task = blockIdx.x * 8 + (threadIdx.x >> 5);
    if (task >= NF * EE) return;
    int e = task / 3;
    int f = task - e * 3;
    int lane = threadIdx.x & 31;

    int   r = ei[e];        // row (scatter target)
    int   c = ei[EE + e];   // col (gather source)
    float a = adj[e];

    if (lane < 24) {
        const float4 v = *(const float4*)(g_T + (size_t)c * FT + f * FOUT + lane * 4);
        float* p = g_ACC + ((size_t)f * NN + r) * FOUT + lane * 4;
        asm volatile("red.global.add.v4.f32 [%0], {%1, %2, %3, %4};"
                     :: "l"(p), "f"(v.x * a), "f"(v.y * a), "f"(v.z * a), "f"(v.w * a)
                     : "memory");
    }
}

// ---------------------------------------------------------------------------
// out[n][c] = bias[c] + sum_f ds[f][n] * relu(ACC[f][n][c])
// ---------------------------------------------------------------------------
__global__ void k_epi(const float* __restrict__ ds,
                      const float* __restrict__ bias,
                      float* __restrict__ out) {
    int n = blockIdx.x;
    int c = threadIdx.x;
    float acc = bias[c];
    #pragma unroll
    for (int f = 0; f < NF; f++) {
        float v = g_ACC[((size_t)f * NN + n) * FOUT + c];
        v = fmaxf(v, 0.0f);
        acc = fmaf(ds[(size_t)f * NN + n], v, acc);
    }
    out[(size_t)n * FOUT + c] = acc;
}

// ---------------------------------------------------------------------------
extern "C" void kernel_launch(void* const* d_in, const int* in_sizes, int n_in,
                              void* d_out, int out_size) {
    const float* x    = (const float*)d_in[0];  // [N, 256]
    const float* adj  = (const float*)d_in[1];  // [E]
    const float* ds   = (const float*)d_in[2];  // [3, N]
    const float* w    = (const float*)d_in[3];  // [3, 256, 96]
    const float* bias = (const float*)d_in[4];  // [96]
    const int*   ei   = (const int*)d_in[5];    // [2, E]
    float* out = (float*)d_out;                 // [N, 96]

    k_deg_init<<<(NN + 255) / 256, 256>>>();
    k_deg_acc<<<(EE + 255) / 256, 256>>>(ei);
    k_gemm<<<dim3((NN + 127) / 128, NF), 256>>>(x, w, ds);
    k_acc_init<<<dim3(NN, NF), FOUT>>>();
    k_spmm<<<(NF * EE + 7) / 8, 256>>>(ei, adj);
    k_epi<<<NN, FOUT>>>(ds, bias, out);
}

// round 2
// speedup vs baseline: 1.3555x; 1.3555x over previous
#include <cuda_runtime.h>
#include <cstdint>

#define NN   50000
#define EE   800000
#define FIN  256
#define FOUT 96
#define NF   3
#define FT   (NF * FOUT)   // 288
#define EPS  0.1f

// Scratch (allocation-free rule: __device__ globals)
__device__ __align__(128) float g_T[(size_t)NN * FT];          // 57.6 MB
__device__ __align__(128) float g_ACC[(size_t)NF * NN * FOUT]; // 57.6 MB
__device__ float g_deg[NN];

// ---------------------------------------------------------------------------
// degree = 1 + count of edges per row
// ---------------------------------------------------------------------------
__global__ void k_deg_init() {
    int i = blockIdx.x * blockDim.x + threadIdx.x;
    if (i < NN) g_deg[i] = 1.0f;
}

__global__ void k_deg_acc(const int* __restrict__ ei) {
    int e = blockIdx.x * blockDim.x + threadIdx.x;
    if (e < EE) atomicAdd(&g_deg[ei[e]], 1.0f);
}

// ---------------------------------------------------------------------------
// Zero the SPMM accumulators (float4 streaming)
// ---------------------------------------------------------------------------
__global__ void k_zero() {
    size_t i = (size_t)blockIdx.x * blockDim.x + threadIdx.x;
    if (i < (size_t)NF * NN * FOUT / 4)
        ((float4*)g_ACC)[i] = make_float4(0.f, 0.f, 0.f, 0.f);
}

// ---------------------------------------------------------------------------
// TF32 split helpers + mma wrapper
// ---------------------------------------------------------------------------
__device__ __forceinline__ void split1(float v, float& h, float& l) {
    uint32_t hu, lu;
    asm("cvt.rna.tf32.f32 %0, %1;" : "=r"(hu) : "f"(v));
    h = __uint_as_float(hu);
    float r = v - h;
    asm("cvt.rna.tf32.f32 %0, %1;" : "=r"(lu) : "f"(r));
    l = __uint_as_float(lu);
}

__device__ __forceinline__ void split4(float4 v, float4& h, float4& l) {
    split1(v.x, h.x, l.x);
    split1(v.y, h.y, l.y);
    split1(v.z, h.z, l.z);
    split1(v.w, h.w, l.w);
}

__device__ __forceinline__ void mma8(float* c, const uint32_t* a,
                                     uint32_t b0, uint32_t b1) {
    asm volatile(
        "mma.sync.aligned.m16n8k8.row.col.f32.tf32.tf32.f32 "
        "{%0,%1,%2,%3}, {%4,%5,%6,%7}, {%8,%9}, {%0,%1,%2,%3};"
        : "+f"(c[0]), "+f"(c[1]), "+f"(c[2]), "+f"(c[3])
        : "r"(a[0]), "r"(a[1]), "r"(a[2]), "r"(a[3]), "r"(b0), "r"(b1));
}

// ---------------------------------------------------------------------------
// T[n][f*96+c] = ds[f][n] * (x @ W_f)[n][c]  via 3xTF32 tensor-core GEMM
// BM=128, BN=96 (blockIdx.y = filter), BK=32, 256 threads (8 warps, 4m x 2n)
// Per warp: 32x48 tile = 2 m-tiles x 6 n-tiles of m16n8k8.
// Smem layouts picked for conflict-free fragment LDS:
//   A: [m][k] stride 36  -> bank = (4m + k) % 32, distinct over (g, t4)
//   B: [k][n] stride 104 -> bank = (8k + n) % 32, distinct over (t4, g)
// ---------------------------------------------------------------------------
#define A_STR 36
#define B_STR 104
#define GEMM_SMEM ((128 * A_STR * 2 + 32 * B_STR * 2) * 4)  // 63488 B

__global__ __launch_bounds__(256) void k_gemm(const float* __restrict__ x,
                                              const float* __restrict__ w,
                                              const float* __restrict__ ds) {
    extern __shared__ float sm[];
    float* Ah = sm;
    float* Al = Ah + 128 * A_STR;
    float* Bh = Al + 128 * A_STR;
    float* Bl = Bh + 32 * B_STR;

    const int m0 = blockIdx.x * 128;
    const int f  = blockIdx.y;
    const float* W = w + (size_t)f * FIN * FOUT;

    const int tid  = threadIdx.x;
    const int wid  = tid >> 5;
    const int lane = tid & 31;
    const int g    = lane >> 2;   // group id 0..7
    const int t4   = lane & 3;    // thread in group 0..3
    const int mw   = (wid & 3) * 32;   // warp m offset
    const int nw   = (wid >> 2) * 48;  // warp n offset

    float c[2][6][4];
    #pragma unroll
    for (int mt = 0; mt < 2; mt++)
        #pragma unroll
        for (int nt = 0; nt < 6; nt++)
            #pragma unroll
            for (int q = 0; q < 4; q++) c[mt][nt][q] = 0.0f;

    for (int k0 = 0; k0 < FIN; k0 += 32) {
        // ---- load + split A tile: 128 x 32 floats (1024 float4, 4/thread)
        #pragma unroll
        for (int i = 0; i < 4; i++) {
            int idx = tid + i * 256;
            int m   = idx >> 3;
            int kq  = (idx & 7) * 4;
            float4 v = make_float4(0.f, 0.f, 0.f, 0.f);
            if (m0 + m < NN)
                v = *(const float4*)(x + (size_t)(m0 + m) * FIN + k0 + kq);
            float4 hv, lv;
            split4(v, hv, lv);
            *(float4*)(Ah + m * A_STR + kq) = hv;
            *(float4*)(Al + m * A_STR + kq) = lv;
        }
        // ---- load + split B tile: 32 x 96 floats (768 float4, 3/thread)
        #pragma unroll
        for (int i = 0; i < 3; i++) {
            int idx = tid + i * 256;
            int k   = idx / 24;
            int q   = (idx - k * 24) * 4;
            float4 v = *(const float4*)(W + (size_t)(k0 + k) * FOUT + q);
            float4 hv, lv;
            split4(v, hv, lv);
            *(float4*)(Bh + k * B_STR + q) = hv;
            *(float4*)(Bl + k * B_STR + q) = lv;
        }
        __syncthreads();

        #pragma unroll
        for (int kk = 0; kk < 32; kk += 8) {
            uint32_t ah[2][4], al[2][4];
            #pragma unroll
            for (int mt = 0; mt < 2; mt++) {
                int mb = mw + mt * 16;
                ah[mt][0] = __float_as_uint(Ah[(mb + g)     * A_STR + kk + t4]);
                ah[mt][1] = __float_as_uint(Ah[(mb + g + 8) * A_STR + kk + t4]);
                ah[mt][2] = __float_as_uint(Ah[(mb + g)     * A_STR + kk + t4 + 4]);
                ah[mt][3] = __float_as_uint(Ah[(mb + g + 8) * A_STR + kk + t4 + 4]);
                al[mt][0] = __float_as_uint(Al[(mb + g)     * A_STR + kk + t4]);
                al[mt][1] = __float_as_uint(Al[(mb + g + 8) * A_STR + kk + t4]);
                al[mt][2] = __float_as_uint(Al[(mb + g)     * A_STR + kk + t4 + 4]);
                al[mt][3] = __float_as_uint(Al[(mb + g + 8) * A_STR + kk + t4 + 4]);
            }
            #pragma unroll
            for (int nt = 0; nt < 6; nt++) {
                int nb = nw + nt * 8 + g;
                uint32_t bh0 = __float_as_uint(Bh[(kk + t4)     * B_STR + nb]);
                uint32_t bh1 = __float_as_uint(Bh[(kk + t4 + 4) * B_STR + nb]);
                uint32_t bl0 = __float_as_uint(Bl[(kk + t4)     * B_STR + nb]);
                uint32_t bl1 = __float_as_uint(Bl[(kk + t4 + 4) * B_STR + nb]);
                #pragma unroll
                for (int mt = 0; mt < 2; mt++) {
                    mma8(c[mt][nt], ah[mt], bh0, bh1);
                    mma8(c[mt][nt], ah[mt], bl0, bl1);
                    mma8(c[mt][nt], al[mt], bh0, bh1);
                }
            }
        }
        __syncthreads();
    }

    // ---- epilogue: scale by d_scales[f][row], store to g_T[row][f*96 + n]
    #pragma unroll
    for (int mt = 0; mt < 2; mt++) {
        int rbase = m0 + mw + mt * 16 + g;
        #pragma unroll
        for (int half = 0; half < 2; half++) {
            int r = rbase + half * 8;
            if (r < NN) {
                float s = ds[(size_t)f * NN + r];
                float* dst = g_T + (size_t)r * FT + f * FOUT + nw;
                #pragma unroll
                for (int nt = 0; nt < 6; nt++) {
                    float2 p;
                    p.x = s * c[mt][nt][half * 2 + 0];
                    p.y = s * c[mt][nt][half * 2 + 1];
                    *(float2*)(dst + nt * 8 + 2 * t4) = p;
                }
            }
        }
    }
}

// ---------------------------------------------------------------------------
// SPMM: for each (edge, filter): ACC[f][row] += adj[e] * T[col][f*96 : +96]
// ---------------------------------------------------------------------------
__global__ __launch_bounds__(256) void k_spmm(const int* __restrict__ ei,
                                              const float* __restrict__ adj) {
    int task = blockIdx.x * 8 + (threadIdx.x >> 5);
    if (task >= NF * EE) return;
    int e = task / 3;
    int f = task - e * 3;
    int lane = threadIdx.x & 31;

    int   r = ei[e];
    int   c = ei[EE + e];
    float a = adj[e];

    if (lane < 24) {
        const float4 v = *(const float4*)(g_T + (size_t)c * FT + f * FOUT + lane * 4);
        float* p = g_ACC + ((size_t)f * NN + r) * FOUT + lane * 4;
        asm volatile("red.global.add.v4.f32 [%0], {%1, %2, %3, %4};"
                     :: "l"(p), "f"(v.x * a), "f"(v.y * a), "f"(v.z * a), "f"(v.w * a)
                     : "memory");
    }
}

// ---------------------------------------------------------------------------
// out[n][c] = bias[c] + sum_f ds[f][n] * relu(ACC[f][n][c] + sign*eps/deg[n]*T[n][f*96+c])
// block (24, 8): x = float4 column, y = node within block
// ---------------------------------------------------------------------------
__global__ void k_epi(const float* __restrict__ ds,
                      const float* __restrict__ bias,
                      float* __restrict__ out) {
    int n  = blockIdx.x * 8 + threadIdx.y;
    int c4 = threadIdx.x * 4;
    float4 o = *(const float4*)(bias + c4);
    float invd = EPS / g_deg[n];
    #pragma unroll
    for (int f = 0; f < NF; f++) {
        float k = ((f == 0) ? -1.0f : 1.0f) * invd;
        float4 a = *(const float4*)(g_ACC + ((size_t)f * NN + n) * FOUT + c4);
        float4 t = *(const float4*)(g_T + (size_t)n * FT + f * FOUT + c4);
        float  d = ds[(size_t)f * NN + n];
        o.x = fmaf(d, fmaxf(fmaf(k, t.x, a.x), 0.f), o.x);
        o.y = fmaf(d, fmaxf(fmaf(k, t.y, a.y), 0.f), o.y);
        o.z = fmaf(d, fmaxf(fmaf(k, t.z, a.z), 0.f), o.z);
        o.w = fmaf(d, fmaxf(fmaf(k, t.w, a.w), 0.f), o.w);
    }
    *(float4*)(out + (size_t)n * FOUT + c4) = o;
}

// ---------------------------------------------------------------------------
extern "C" void kernel_launch(void* const* d_in, const int* in_sizes, int n_in,
                              void* d_out, int out_size) {
    const float* x    = (const float*)d_in[0];  // [N, 256]
    const float* adj  = (const float*)d_in[1];  // [E]
    const float* ds   = (const float*)d_in[2];  // [3, N]
    const float* w    = (const float*)d_in[3];  // [3, 256, 96]
    const float* bias = (const float*)d_in[4];  // [96]
    const int*   ei   = (const int*)d_in[5];    // [2, E]
    float* out = (float*)d_out;                 // [N, 96]

    cudaFuncSetAttribute(k_gemm, cudaFuncAttributeMaxDynamicSharedMemorySize,
                         GEMM_SMEM);

    k_deg_init<<<(NN + 255) / 256, 256>>>();
    k_deg_acc<<<(EE + 255) / 256, 256>>>(ei);
    k_zero<<<(NF * NN * FOUT / 4 + 255) / 256, 256>>>();
    k_gemm<<<dim3((NN + 127) / 128, NF), 256, GEMM_SMEM>>>(x, w, ds);
    k_spmm<<<(NF * EE + 7) / 8, 256>>>(ei, adj);
    k_epi<<<NN / 8, dim3(24, 8)>>>(ds, bias, out);
}

// round 3
// speedup vs baseline: 2.6905x; 1.9848x over previous
#include <cuda_runtime.h>
#include <cstdint>

#define NN   50000
#define EE   800000
#define FIN  256
#define FOUT 96
#define NF   3
#define FT   (NF * FOUT)   // 288
#define EPS  0.1f

#define SCAN_B 1024
#define NBLK   ((NN + SCAN_B - 1) / SCAN_B)   // 49

// Scratch (allocation-free rule: __device__ globals)
__device__ __align__(128) float g_T[(size_t)NN * FT];   // 57.6 MB
__device__ int   g_cnt[NN];
__device__ int   g_start[NN];
__device__ int   g_cursor[NN];
__device__ int   g_part[NBLK];
__device__ __align__(16) int   g_csr_col[EE];
__device__ __align__(16) float g_csr_val[EE];

// ---------------------------------------------------------------------------
// CSR build: histogram -> exclusive scan -> scatter
// ---------------------------------------------------------------------------
__global__ void k_cnt0() {
    int i = blockIdx.x * blockDim.x + threadIdx.x;
    if (i < NN) g_cnt[i] = 0;
}

__global__ void k_hist(const int* __restrict__ ei) {
    int e = blockIdx.x * blockDim.x + threadIdx.x;
    if (e < EE) atomicAdd(&g_cnt[ei[e]], 1);
}

__global__ __launch_bounds__(SCAN_B) void k_scan1() {
    __shared__ int s[SCAN_B];
    int i = blockIdx.x * SCAN_B + threadIdx.x;
    int v = (i < NN) ? g_cnt[i] : 0;
    s[threadIdx.x] = v;
    __syncthreads();
    #pragma unroll
    for (int off = 1; off < SCAN_B; off <<= 1) {
        int t = (threadIdx.x >= off) ? s[threadIdx.x - off] : 0;
        __syncthreads();
        s[threadIdx.x] += t;
        __syncthreads();
    }
    if (i < NN) g_start[i] = s[threadIdx.x] - v;   // block-local exclusive
    if (threadIdx.x == SCAN_B - 1) g_part[blockIdx.x] = s[SCAN_B - 1];
}

__global__ void k_scan2() {
    // exclusive scan of NBLK=49 partials; trivial serial
    int run = 0;
    for (int b = 0; b < NBLK; b++) {
        int v = g_part[b];
        g_part[b] = run;
        run += v;
    }
}

__global__ __launch_bounds__(SCAN_B) void k_scan3() {
    int i = blockIdx.x * SCAN_B + threadIdx.x;
    if (i < NN) {
        int s = g_start[i] + g_part[blockIdx.x];
        g_start[i]  = s;
        g_cursor[i] = s;
    }
}

__global__ void k_scatter(const int* __restrict__ ei,
                          const float* __restrict__ adj) {
    int e = blockIdx.x * blockDim.x + threadIdx.x;
    if (e < EE) {
        int r = ei[e];
        int pos = atomicAdd(&g_cursor[r], 1);
        g_csr_col[pos] = ei[EE + e];
        g_csr_val[pos] = adj[e];
    }
}

// ---------------------------------------------------------------------------
// TF32 split helpers + mma wrapper
// ---------------------------------------------------------------------------
__device__ __forceinline__ void split1(float v, float& h, float& l) {
    uint32_t hu, lu;
    asm("cvt.rna.tf32.f32 %0, %1;" : "=r"(hu) : "f"(v));
    h = __uint_as_float(hu);
    float r = v - h;
    asm("cvt.rna.tf32.f32 %0, %1;" : "=r"(lu) : "f"(r));
    l = __uint_as_float(lu);
}

__device__ __forceinline__ void split4(float4 v, float4& h, float4& l) {
    split1(v.x, h.x, l.x);
    split1(v.y, h.y, l.y);
    split1(v.z, h.z, l.z);
    split1(v.w, h.w, l.w);
}

__device__ __forceinline__ void mma8(float* c, const uint32_t* a,
                                     uint32_t b0, uint32_t b1) {
    asm volatile(
        "mma.sync.aligned.m16n8k8.row.col.f32.tf32.tf32.f32 "
        "{%0,%1,%2,%3}, {%4,%5,%6,%7}, {%8,%9}, {%0,%1,%2,%3};"
        : "+f"(c[0]), "+f"(c[1]), "+f"(c[2]), "+f"(c[3])
        : "r"(a[0]), "r"(a[1]), "r"(a[2]), "r"(a[3]), "r"(b0), "r"(b1));
}

// ---------------------------------------------------------------------------
// T[n][f*96+c] = ds[f][n] * (x @ W_f)[n][c]  via 3xTF32 tensor-core GEMM
// (unchanged from round 2 — 123us, tensor=59%)
// ---------------------------------------------------------------------------
#define A_STR 36
#define B_STR 104
#define GEMM_SMEM ((128 * A_STR * 2 + 32 * B_STR * 2) * 4)  // 63488 B

__global__ __launch_bounds__(256) void k_gemm(const float* __restrict__ x,
                                              const float* __restrict__ w,
                                              const float* __restrict__ ds) {
    extern __shared__ float sm[];
    float* Ah = sm;
    float* Al = Ah + 128 * A_STR;
    float* Bh = Al + 128 * A_STR;
    float* Bl = Bh + 32 * B_STR;

    const int m0 = blockIdx.x * 128;
    const int f  = blockIdx.y;
    const float* W = w + (size_t)f * FIN * FOUT;

    const int tid  = threadIdx.x;
    const int wid  = tid >> 5;
    const int lane = tid & 31;
    const int g    = lane >> 2;
    const int t4   = lane & 3;
    const int mw   = (wid & 3) * 32;
    const int nw   = (wid >> 2) * 48;

    float c[2][6][4];
    #pragma unroll
    for (int mt = 0; mt < 2; mt++)
        #pragma unroll
        for (int nt = 0; nt < 6; nt++)
            #pragma unroll
            for (int q = 0; q < 4; q++) c[mt][nt][q] = 0.0f;

    for (int k0 = 0; k0 < FIN; k0 += 32) {
        #pragma unroll
        for (int i = 0; i < 4; i++) {
            int idx = tid + i * 256;
            int m   = idx >> 3;
            int kq  = (idx & 7) * 4;
            float4 v = make_float4(0.f, 0.f, 0.f, 0.f);
            if (m0 + m < NN)
                v = *(const float4*)(x + (size_t)(m0 + m) * FIN + k0 + kq);
            float4 hv, lv;
            split4(v, hv, lv);
            *(float4*)(Ah + m * A_STR + kq) = hv;
            *(float4*)(Al + m * A_STR + kq) = lv;
        }
        #pragma unroll
        for (int i = 0; i < 3; i++) {
            int idx = tid + i * 256;
            int k   = idx / 24;
            int q   = (idx - k * 24) * 4;
            float4 v = *(const float4*)(W + (size_t)(k0 + k) * FOUT + q);
            float4 hv, lv;
            split4(v, hv, lv);
            *(float4*)(Bh + k * B_STR + q) = hv;
            *(float4*)(Bl + k * B_STR + q) = lv;
        }
        __syncthreads();

        #pragma unroll
        for (int kk = 0; kk < 32; kk += 8) {
            uint32_t ah[2][4], al[2][4];
            #pragma unroll
            for (int mt = 0; mt < 2; mt++) {
                int mb = mw + mt * 16;
                ah[mt][0] = __float_as_uint(Ah[(mb + g)     * A_STR + kk + t4]);
                ah[mt][1] = __float_as_uint(Ah[(mb + g + 8) * A_STR + kk + t4]);
                ah[mt][2] = __float_as_uint(Ah[(mb + g)     * A_STR + kk + t4 + 4]);
                ah[mt][3] = __float_as_uint(Ah[(mb + g + 8) * A_STR + kk + t4 + 4]);
                al[mt][0] = __float_as_uint(Al[(mb + g)     * A_STR + kk + t4]);
                al[mt][1] = __float_as_uint(Al[(mb + g + 8) * A_STR + kk + t4]);
                al[mt][2] = __float_as_uint(Al[(mb + g)     * A_STR + kk + t4 + 4]);
                al[mt][3] = __float_as_uint(Al[(mb + g + 8) * A_STR + kk + t4 + 4]);
            }
            #pragma unroll
            for (int nt = 0; nt < 6; nt++) {
                int nb = nw + nt * 8 + g;
                uint32_t bh0 = __float_as_uint(Bh[(kk + t4)     * B_STR + nb]);
                uint32_t bh1 = __float_as_uint(Bh[(kk + t4 + 4) * B_STR + nb]);
                uint32_t bl0 = __float_as_uint(Bl[(kk + t4)     * B_STR + nb]);
                uint32_t bl1 = __float_as_uint(Bl[(kk + t4 + 4) * B_STR + nb]);
                #pragma unroll
                for (int mt = 0; mt < 2; mt++) {
                    mma8(c[mt][nt], ah[mt], bh0, bh1);
                    mma8(c[mt][nt], ah[mt], bl0, bl1);
                    mma8(c[mt][nt], al[mt], bh0, bh1);
                }
            }
        }
        __syncthreads();
    }

    #pragma unroll
    for (int mt = 0; mt < 2; mt++) {
        int rbase = m0 + mw + mt * 16 + g;
        #pragma unroll
        for (int half = 0; half < 2; half++) {
            int r = rbase + half * 8;
            if (r < NN) {
                float s = ds[(size_t)f * NN + r];
                float* dst = g_T + (size_t)r * FT + f * FOUT + nw;
                #pragma unroll
                for (int nt = 0; nt < 6; nt++) {
                    float2 p;
                    p.x = s * c[mt][nt][half * 2 + 0];
                    p.y = s * c[mt][nt][half * 2 + 1];
                    *(float2*)(dst + nt * 8 + 2 * t4) = p;
                }
            }
        }
    }
}

// ---------------------------------------------------------------------------
// Fused SPMM + diag + relu + scale + bias + out.
// One warp per row; 24 active lanes; lane l holds float4 cols [4l,4l+4)
// for all 3 filters (indices l, l+24, l+48 into the 72-float4 g_T row).
// ---------------------------------------------------------------------------
__device__ __forceinline__ float4 fma4(float a, float4 v, float4 c) {
    c.x = fmaf(a, v.x, c.x);
    c.y = fmaf(a, v.y, c.y);
    c.z = fmaf(a, v.z, c.z);
    c.w = fmaf(a, v.w, c.w);
    return c;
}

__device__ __forceinline__ float4 relu4(float4 v) {
    return make_float4(fmaxf(v.x, 0.f), fmaxf(v.y, 0.f),
                       fmaxf(v.z, 0.f), fmaxf(v.w, 0.f));
}

__global__ __launch_bounds__(256) void k_spmm(const float* __restrict__ ds,
                                              const float* __restrict__ bias,
                                              float* __restrict__ out) {
    int r = blockIdx.x * 8 + (threadIdx.x >> 5);
    int l = threadIdx.x & 31;
    if (r >= NN || l >= 24) return;

    const float4* __restrict__ T4 = (const float4*)g_T;
    int beg = g_start[r];
    int cnt = g_cnt[r];
    int end = beg + cnt;

    float4 a0 = make_float4(0.f, 0.f, 0.f, 0.f);
    float4 a1 = a0, a2 = a0;

    int e = beg;
    // unroll-by-2 with explicit prefetch of both edge headers
    for (; e + 1 < end; e += 2) {
        int   c0 = g_csr_col[e],     c1 = g_csr_col[e + 1];
        float v0 = g_csr_val[e],     v1 = g_csr_val[e + 1];
        const float4* p0 = T4 + (size_t)c0 * 72;
        const float4* p1 = T4 + (size_t)c1 * 72;
        float4 x0 = p0[l], x1 = p0[l + 24], x2 = p0[l + 48];
        float4 y0 = p1[l], y1 = p1[l + 24], y2 = p1[l + 48];
        a0 = fma4(v0, x0, a0); a1 = fma4(v0, x1, a1); a2 = fma4(v0, x2, a2);
        a0 = fma4(v1, y0, a0); a1 = fma4(v1, y1, a1); a2 = fma4(v1, y2, a2);
    }
    if (e < end) {
        int   c0 = g_csr_col[e];
        float v0 = g_csr_val[e];
        const float4* p0 = T4 + (size_t)c0 * 72;
        a0 = fma4(v0, p0[l], a0);
        a1 = fma4(v0, p0[l + 24], a1);
        a2 = fma4(v0, p0[l + 48], a2);
    }

    // diagonal term: sign_f * EPS/deg * T[r]  (deg = cnt + 1 self loop)
    float k = EPS / ((float)cnt + 1.0f);
    const float4* pr = T4 + (size_t)r * 72;
    a0 = fma4(-k, pr[l],      a0);
    a1 = fma4( k, pr[l + 24], a1);
    a2 = fma4( k, pr[l + 48], a2);

    // epilogue: out = bias + sum_f ds[f][r] * relu(acc_f)
    float d0 = ds[r];
    float d1 = ds[NN + r];
    float d2 = ds[2 * NN + r];
    float4 o = ((const float4*)bias)[l];
    o = fma4(d0, relu4(a0), o);
    o = fma4(d1, relu4(a1), o);
    o = fma4(d2, relu4(a2), o);
    ((float4*)out)[(size_t)r * 24 + l] = o;
}

// ---------------------------------------------------------------------------
extern "C" void kernel_launch(void* const* d_in, const int* in_sizes, int n_in,
                              void* d_out, int out_size) {
    const float* x    = (const float*)d_in[0];  // [N, 256]
    const float* adj  = (const float*)d_in[1];  // [E]
    const float* ds   = (const float*)d_in[2];  // [3, N]
    const float* w    = (const float*)d_in[3];  // [3, 256, 96]
    const float* bias = (const float*)d_in[4];  // [96]
    const int*   ei   = (const int*)d_in[5];    // [2, E]
    float* out = (float*)d_out;                 // [N, 96]

    cudaFuncSetAttribute(k_gemm, cudaFuncAttributeMaxDynamicSharedMemorySize,
                         GEMM_SMEM);

    k_cnt0<<<(NN + 255) / 256, 256>>>();
    k_hist<<<(EE + 255) / 256, 256>>>(ei);
    k_scan1<<<NBLK, SCAN_B>>>();
    k_scan2<<<1, 1>>>();
    k_scan3<<<NBLK, SCAN_B>>>();
    k_scatter<<<(EE + 255) / 256, 256>>>(ei, adj);
    k_gemm<<<dim3((NN + 127) / 128, NF), 256, GEMM_SMEM>>>(x, w, ds);
    k_spmm<<<(NN + 7) / 8, 256>>>(ds, bias, out);
}

// round 4
// speedup vs baseline: 2.9216x; 1.0859x over previous
#include <cuda_runtime.h>
#include <cstdint>

#define NN   50000
#define EE   800000
#define FIN  256
#define FOUT 96
#define NF   3
#define FT   (NF * FOUT)   // 288
#define EPS  0.1f

#define SCAN_B 1024
#define NBLK   ((NN + SCAN_B - 1) / SCAN_B)   // 49

// Scratch (allocation-free rule: __device__ globals)
__device__ __align__(128) float g_T[(size_t)NN * FT];   // 57.6 MB
__device__ __align__(128) float g_Wh[NF * FIN * FOUT];  // pre-split W hi
__device__ __align__(128) float g_Wl[NF * FIN * FOUT];  // pre-split W lo
__device__ int   g_cnt[NN];
__device__ int   g_start[NN];
__device__ int   g_cursor[NN];
__device__ int   g_part[NBLK];
__device__ __align__(16) int   g_csr_col[EE];
__device__ __align__(16) float g_csr_val[EE];

// ---------------------------------------------------------------------------
// CSR build: histogram -> exclusive scan -> scatter  (runs on side stream,
// overlapped with wsplit+gemm)
// ---------------------------------------------------------------------------
__global__ void k_cnt0() {
    int i = blockIdx.x * blockDim.x + threadIdx.x;
    if (i < NN) g_cnt[i] = 0;
}

__global__ void k_hist(const int* __restrict__ ei) {
    int e = blockIdx.x * blockDim.x + threadIdx.x;
    if (e < EE) atomicAdd(&g_cnt[ei[e]], 1);
}

__global__ __launch_bounds__(SCAN_B) void k_scan1() {
    __shared__ int s[SCAN_B];
    int i = blockIdx.x * SCAN_B + threadIdx.x;
    int v = (i < NN) ? g_cnt[i] : 0;
    s[threadIdx.x] = v;
    __syncthreads();
    #pragma unroll
    for (int off = 1; off < SCAN_B; off <<= 1) {
        int t = (threadIdx.x >= off) ? s[threadIdx.x - off] : 0;
        __syncthreads();
        s[threadIdx.x] += t;
        __syncthreads();
    }
    if (i < NN) g_start[i] = s[threadIdx.x] - v;   // block-local exclusive
    if (threadIdx.x == SCAN_B - 1) g_part[blockIdx.x] = s[SCAN_B - 1];
}

__global__ void k_scan2() {
    int run = 0;
    for (int b = 0; b < NBLK; b++) {
        int v = g_part[b];
        g_part[b] = run;
        run += v;
    }
}

__global__ __launch_bounds__(SCAN_B) void k_scan3() {
    int i = blockIdx.x * SCAN_B + threadIdx.x;
    if (i < NN) {
        int s = g_start[i] + g_part[blockIdx.x];
        g_start[i]  = s;
        g_cursor[i] = s;
    }
}

__global__ void k_scatter(const int* __restrict__ ei,
                          const float* __restrict__ adj) {
    int e = blockIdx.x * blockDim.x + threadIdx.x;
    if (e < EE) {
        int r = ei[e];
        int pos = atomicAdd(&g_cursor[r], 1);
        g_csr_col[pos] = ei[EE + e];
        g_csr_val[pos] = adj[e];
    }
}

// ---------------------------------------------------------------------------
// TF32 split helpers + mma wrapper + cp.async
// ---------------------------------------------------------------------------
__device__ __forceinline__ void split1(float v, float& h, float& l) {
    uint32_t hu, lu;
    asm("cvt.rna.tf32.f32 %0, %1;" : "=r"(hu) : "f"(v));
    h = __uint_as_float(hu);
    float r = v - h;
    asm("cvt.rna.tf32.f32 %0, %1;" : "=r"(lu) : "f"(r));
    l = __uint_as_float(lu);
}

__device__ __forceinline__ void split4(float4 v, float4& h, float4& l) {
    split1(v.x, h.x, l.x);
    split1(v.y, h.y, l.y);
    split1(v.z, h.z, l.z);
    split1(v.w, h.w, l.w);
}

__device__ __forceinline__ void mma8(float* c, const uint32_t* a,
                                     uint32_t b0, uint32_t b1) {
    asm volatile(
        "mma.sync.aligned.m16n8k8.row.col.f32.tf32.tf32.f32 "
        "{%0,%1,%2,%3}, {%4,%5,%6,%7}, {%8,%9}, {%0,%1,%2,%3};"
        : "+f"(c[0]), "+f"(c[1]), "+f"(c[2]), "+f"(c[3])
        : "r"(a[0]), "r"(a[1]), "r"(a[2]), "r"(a[3]), "r"(b0), "r"(b1));
}

__device__ __forceinline__ void cpa16(float* smem, const float* g) {
    uint32_t s = (uint32_t)__cvta_generic_to_shared(smem);
    asm volatile("cp.async.ca.shared.global [%0], [%1], 16;"
                 :: "r"(s), "l"(g));
}

// one-time pre-split of W (288KB, L2-resident afterwards)
__global__ void k_wsplit(const float* __restrict__ w) {
    int i = blockIdx.x * blockDim.x + threadIdx.x;
    if (i < NF * FIN * FOUT)
        split1(w[i], g_Wh[i], g_Wl[i]);
}

// ---------------------------------------------------------------------------
// T[n][f*96+c] = ds[f][n] * (x @ W_f)[n][c]  via 3xTF32 tensor-core GEMM
// BM=128, BN=96 (blockIdx.y = filter), BK=32, 256 threads (8 warps, 4m x 2n)
// Pipeline: A tile prefetched into regs during compute; B fetched pre-split
// via cp.async (no cvt on B path).
// ---------------------------------------------------------------------------
#define A_STR 36
#define B_STR 104
#define GEMM_SMEM ((128 * A_STR * 2 + 32 * B_STR * 2) * 4)  // 63488 B

__global__ __launch_bounds__(256, 2) void k_gemm(const float* __restrict__ x,
                                                 const float* __restrict__ ds) {
    extern __shared__ float sm[];
    float* Ah = sm;
    float* Al = Ah + 128 * A_STR;
    float* Bh = Al + 128 * A_STR;
    float* Bl = Bh + 32 * B_STR;

    const int m0 = blockIdx.x * 128;
    const int f  = blockIdx.y;
    const float* Wh = g_Wh + (size_t)f * FIN * FOUT;
    const float* Wl = g_Wl + (size_t)f * FIN * FOUT;

    const int tid  = threadIdx.x;
    const int wid  = tid >> 5;
    const int lane = tid & 31;
    const int g    = lane >> 2;
    const int t4   = lane & 3;
    const int mw   = (wid & 3) * 32;
    const int nw   = (wid >> 2) * 48;

    // per-thread A-load geometry (constant across k iterations)
    int am[4], akq[4];
    bool aok[4];
    #pragma unroll
    for (int i = 0; i < 4; i++) {
        int idx = tid + i * 256;
        am[i]  = idx >> 3;
        akq[i] = (idx & 7) * 4;
        aok[i] = (m0 + am[i]) < NN;
    }
    // per-thread B-load geometry
    int bk[3], bq[3];
    #pragma unroll
    for (int i = 0; i < 3; i++) {
        int idx = tid + i * 256;
        bk[i] = idx / 24;
        bq[i] = (idx - bk[i] * 24) * 4;
    }

    float c[2][6][4];
    #pragma unroll
    for (int mt = 0; mt < 2; mt++)
        #pragma unroll
        for (int nt = 0; nt < 6; nt++)
            #pragma unroll
            for (int q = 0; q < 4; q++) c[mt][nt][q] = 0.0f;

    // prologue: prefetch A tile for k0 = 0
    float4 areg[4];
    #pragma unroll
    for (int i = 0; i < 4; i++)
        areg[i] = aok[i]
            ? *(const float4*)(x + (size_t)(m0 + am[i]) * FIN + akq[i])
            : make_float4(0.f, 0.f, 0.f, 0.f);

    for (int k0 = 0; k0 < FIN; k0 += 32) {
        // issue B cp.asyncs (pre-split hi/lo, gmem -> smem, no registers)
        #pragma unroll
        for (int i = 0; i < 3; i++) {
            const float* srcH = Wh + (size_t)(k0 + bk[i]) * FOUT + bq[i];
            const float* srcL = Wl + (size_t)(k0 + bk[i]) * FOUT + bq[i];
            cpa16(Bh + bk[i] * B_STR + bq[i], srcH);
            cpa16(Bl + bk[i] * B_STR + bq[i], srcL);
        }
        asm volatile("cp.async.commit_group;");

        // split prefetched A -> smem
        #pragma unroll
        for (int i = 0; i < 4; i++) {
            float4 hv, lv;
            split4(areg[i], hv, lv);
            *(float4*)(Ah + am[i] * A_STR + akq[i]) = hv;
            *(float4*)(Al + am[i] * A_STR + akq[i]) = lv;
        }

        asm volatile("cp.async.wait_group 0;");
        __syncthreads();

        // prefetch next A tile into regs (hidden under MMAs)
        if (k0 + 32 < FIN) {
            #pragma unroll
            for (int i = 0; i < 4; i++)
                areg[i] = aok[i]
                    ? *(const float4*)(x + (size_t)(m0 + am[i]) * FIN + k0 + 32 + akq[i])
                    : make_float4(0.f, 0.f, 0.f, 0.f);
        }

        #pragma unroll
        for (int kk = 0; kk < 32; kk += 8) {
            uint32_t ah[2][4], al[2][4];
            #pragma unroll
            for (int mt = 0; mt < 2; mt++) {
                int mb = mw + mt * 16;
                ah[mt][0] = __float_as_uint(Ah[(mb + g)     * A_STR + kk + t4]);
                ah[mt][1] = __float_as_uint(Ah[(mb + g + 8) * A_STR + kk + t4]);
                ah[mt][2] = __float_as_uint(Ah[(mb + g)     * A_STR + kk + t4 + 4]);
                ah[mt][3] = __float_as_uint(Ah[(mb + g + 8) * A_STR + kk + t4 + 4]);
                al[mt][0] = __float_as_uint(Al[(mb + g)     * A_STR + kk + t4]);
                al[mt][1] = __float_as_uint(Al[(mb + g + 8) * A_STR + kk + t4]);
                al[mt][2] = __float_as_uint(Al[(mb + g)     * A_STR + kk + t4 + 4]);
                al[mt][3] = __float_as_uint(Al[(mb + g + 8) * A_STR + kk + t4 + 4]);
            }
            #pragma unroll
            for (int nt = 0; nt < 6; nt++) {
                int nb = nw + nt * 8 + g;
                uint32_t bh0 = __float_as_uint(Bh[(kk + t4)     * B_STR + nb]);
                uint32_t bh1 = __float_as_uint(Bh[(kk + t4 + 4) * B_STR + nb]);
                uint32_t bl0 = __float_as_uint(Bl[(kk + t4)     * B_STR + nb]);
                uint32_t bl1 = __float_as_uint(Bl[(kk + t4 + 4) * B_STR + nb]);
                #pragma unroll
                for (int mt = 0; mt < 2; mt++) {
                    mma8(c[mt][nt], ah[mt], bh0, bh1);
                    mma8(c[mt][nt], ah[mt], bl0, bl1);
                    mma8(c[mt][nt], al[mt], bh0, bh1);
                }
            }
        }
        __syncthreads();
    }

    // epilogue: scale by d_scales[f][row], store to g_T[row][f*96 + n]
    #pragma unroll
    for (int mt = 0; mt < 2; mt++) {
        int rbase = m0 + mw + mt * 16 + g;
        #pragma unroll
        for (int half = 0; half < 2; half++) {
            int r = rbase + half * 8;
            if (r < NN) {
                float s = ds[(size_t)f * NN + r];
                float* dst = g_T + (size_t)r * FT + f * FOUT + nw;
                #pragma unroll
                for (int nt = 0; nt < 6; nt++) {
                    float2 p;
                    p.x = s * c[mt][nt][half * 2 + 0];
                    p.y = s * c[mt][nt][half * 2 + 1];
                    *(float2*)(dst + nt * 8 + 2 * t4) = p;
                }
            }
        }
    }
}

// ---------------------------------------------------------------------------
// Fused SPMM + diag + relu + scale + bias + out.  One warp per row.
// ---------------------------------------------------------------------------
__device__ __forceinline__ float4 fma4(float a, float4 v, float4 c) {
    c.x = fmaf(a, v.x, c.x);
    c.y = fmaf(a, v.y, c.y);
    c.z = fmaf(a, v.z, c.z);
    c.w = fmaf(a, v.w, c.w);
    return c;
}

__device__ __forceinline__ float4 relu4(float4 v) {
    return make_float4(fmaxf(v.x, 0.f), fmaxf(v.y, 0.f),
                       fmaxf(v.z, 0.f), fmaxf(v.w, 0.f));
}

__global__ __launch_bounds__(256) void k_spmm(const float* __restrict__ ds,
                                              const float* __restrict__ bias,
                                              float* __restrict__ out) {
    int r = blockIdx.x * 8 + (threadIdx.x >> 5);
    int l = threadIdx.x & 31;
    if (r >= NN || l >= 24) return;

    const float4* __restrict__ T4 = (const float4*)g_T;
    int beg = g_start[r];
    int cnt = g_cnt[r];
    int end = beg + cnt;

    float4 a0 = make_float4(0.f, 0.f, 0.f, 0.f);
    float4 a1 = a0, a2 = a0;

    int e = beg;
    for (; e + 1 < end; e += 2) {
        int   c0 = g_csr_col[e],     c1 = g_csr_col[e + 1];
        float v0 = g_csr_val[e],     v1 = g_csr_val[e + 1];
        const float4* p0 = T4 + (size_t)c0 * 72;
        const float4* p1 = T4 + (size_t)c1 * 72;
        float4 x0 = p0[l], x1 = p0[l + 24], x2 = p0[l + 48];
        float4 y0 = p1[l], y1 = p1[l + 24], y2 = p1[l + 48];
        a0 = fma4(v0, x0, a0); a1 = fma4(v0, x1, a1); a2 = fma4(v0, x2, a2);
        a0 = fma4(v1, y0, a0); a1 = fma4(v1, y1, a1); a2 = fma4(v1, y2, a2);
    }
    if (e < end) {
        int   c0 = g_csr_col[e];
        float v0 = g_csr_val[e];
        const float4* p0 = T4 + (size_t)c0 * 72;
        a0 = fma4(v0, p0[l], a0);
        a1 = fma4(v0, p0[l + 24], a1);
        a2 = fma4(v0, p0[l + 48], a2);
    }

    // diagonal term: sign_f * EPS/deg * T[r]  (deg = cnt + 1 self loop)
    float k = EPS / ((float)cnt + 1.0f);
    const float4* pr = T4 + (size_t)r * 72;
    a0 = fma4(-k, pr[l],      a0);
    a1 = fma4( k, pr[l + 24], a1);
    a2 = fma4( k, pr[l + 48], a2);

    float d0 = ds[r];
    float d1 = ds[NN + r];
    float d2 = ds[2 * NN + r];
    float4 o = ((const float4*)bias)[l];
    o = fma4(d0, relu4(a0), o);
    o = fma4(d1, relu4(a1), o);
    o = fma4(d2, relu4(a2), o);
    ((float4*)out)[(size_t)r * 24 + l] = o;
}

// ---------------------------------------------------------------------------
extern "C" void kernel_launch(void* const* d_in, const int* in_sizes, int n_in,
                              void* d_out, int out_size) {
    const float* x    = (const float*)d_in[0];  // [N, 256]
    const float* adj  = (const float*)d_in[1];  // [E]
    const float* ds   = (const float*)d_in[2];  // [3, N]
    const float* w    = (const float*)d_in[3];  // [3, 256, 96]
    const float* bias = (const float*)d_in[4];  // [96]
    const int*   ei   = (const int*)d_in[5];    // [2, E]
    float* out = (float*)d_out;                 // [N, 96]

    // one-time resources (created on the eager correctness call; the capture
    // call re-records the same ops, producing identical graph work each time)
    static cudaStream_t s2 = nullptr;
    static cudaEvent_t evFork = nullptr, evJoin = nullptr;
    if (!s2) {
        cudaStreamCreateWithFlags(&s2, cudaStreamNonBlocking);
        cudaEventCreateWithFlags(&evFork, cudaEventDisableTiming);
        cudaEventCreateWithFlags(&evJoin, cudaEventDisableTiming);
        cudaFuncSetAttribute(k_gemm, cudaFuncAttributeMaxDynamicSharedMemorySize,
                             GEMM_SMEM);
    }

    // fork: CSR build on s2, concurrent with wsplit+gemm on the main stream
    cudaEventRecord(evFork, 0);
    cudaStreamWaitEvent(s2, evFork, 0);

    k_cnt0<<<(NN + 255) / 256, 256, 0, s2>>>();
    k_hist<<<(EE + 255) / 256, 256, 0, s2>>>(ei);
    k_scan1<<<NBLK, SCAN_B, 0, s2>>>();
    k_scan2<<<1, 1, 0, s2>>>();
    k_scan3<<<NBLK, SCAN_B, 0, s2>>>();
    k_scatter<<<(EE + 255) / 256, 256, 0, s2>>>(ei, adj);
    cudaEventRecord(evJoin, s2);

    k_wsplit<<<(NF * FIN * FOUT + 255) / 256, 256>>>(w);
    k_gemm<<<dim3((NN + 127) / 128, NF), 256, GEMM_SMEM>>>(x, ds);

    // join, then fused SPMM + epilogue
    cudaStreamWaitEvent(0, evJoin, 0);
    k_spmm<<<(NN + 7) / 8, 256>>>(ds, bias, out);
}

// round 5
// speedup vs baseline: 3.5675x; 1.2211x over previous
#include <cuda_runtime.h>
#include <cuda_fp16.h>
#include <cstdint>

#define NN   50000
#define EE   800000
#define FIN  256
#define FOUT 96
#define NF   3
#define FT   (NF * FOUT)   // 288
#define EPS  0.1f

#define SCAN_B 1024
#define NBLK   ((NN + SCAN_B - 1) / SCAN_B)   // 49

// Scratch (allocation-free rule: __device__ globals)
__device__ __align__(128) __half g_Th[(size_t)NN * FT];  // 28.8 MB (L2-resident)
__device__ __align__(128) float  g_Wh[NF * FIN * FOUT];  // tf32-truncated W
__device__ int   g_cnt[NN];
__device__ int   g_start[NN];
__device__ int   g_cursor[NN];
__device__ int   g_part[NBLK];
__device__ __align__(16) int   g_csr_col[EE];
__device__ __align__(16) float g_csr_val[EE];

// ---------------------------------------------------------------------------
// CSR build (overlapped on side stream with wsplit+gemm)
// ---------------------------------------------------------------------------
__global__ void k_cnt0() {
    int i = blockIdx.x * blockDim.x + threadIdx.x;
    if (i < NN) g_cnt[i] = 0;
}

__global__ void k_hist(const int* __restrict__ ei) {
    int e = blockIdx.x * blockDim.x + threadIdx.x;
    if (e < EE) atomicAdd(&g_cnt[ei[e]], 1);
}

__global__ __launch_bounds__(SCAN_B) void k_scan1() {
    __shared__ int s[SCAN_B];
    int i = blockIdx.x * SCAN_B + threadIdx.x;
    int v = (i < NN) ? g_cnt[i] : 0;
    s[threadIdx.x] = v;
    __syncthreads();
    #pragma unroll
    for (int off = 1; off < SCAN_B; off <<= 1) {
        int t = (threadIdx.x >= off) ? s[threadIdx.x - off] : 0;
        __syncthreads();
        s[threadIdx.x] += t;
        __syncthreads();
    }
    if (i < NN) g_start[i] = s[threadIdx.x] - v;
    if (threadIdx.x == SCAN_B - 1) g_part[blockIdx.x] = s[SCAN_B - 1];
}

__global__ void k_scan2() {
    int run = 0;
    for (int b = 0; b < NBLK; b++) {
        int v = g_part[b];
        g_part[b] = run;
        run += v;
    }
}

__global__ __launch_bounds__(SCAN_B) void k_scan3() {
    int i = blockIdx.x * SCAN_B + threadIdx.x;
    if (i < NN) {
        int s = g_start[i] + g_part[blockIdx.x];
        g_start[i]  = s;
        g_cursor[i] = s;
    }
}

__global__ void k_scatter(const int* __restrict__ ei,
                          const float* __restrict__ adj) {
    int e = blockIdx.x * blockDim.x + threadIdx.x;
    if (e < EE) {
        int r = ei[e];
        int pos = atomicAdd(&g_cursor[r], 1);
        g_csr_col[pos] = ei[EE + e];
        g_csr_val[pos] = adj[e];
    }
}

// ---------------------------------------------------------------------------
// TF32 helpers + mma wrapper + cp.async
// ---------------------------------------------------------------------------
__device__ __forceinline__ void split1(float v, float& h, float& l) {
    uint32_t hu, lu;
    asm("cvt.rna.tf32.f32 %0, %1;" : "=r"(hu) : "f"(v));
    h = __uint_as_float(hu);
    float r = v - h;
    asm("cvt.rna.tf32.f32 %0, %1;" : "=r"(lu) : "f"(r));
    l = __uint_as_float(lu);
}

__device__ __forceinline__ void split4(float4 v, float4& h, float4& l) {
    split1(v.x, h.x, l.x);
    split1(v.y, h.y, l.y);
    split1(v.z, h.z, l.z);
    split1(v.w, h.w, l.w);
}

__device__ __forceinline__ void mma8(float* c, const uint32_t* a,
                                     uint32_t b0, uint32_t b1) {
    asm volatile(
        "mma.sync.aligned.m16n8k8.row.col.f32.tf32.tf32.f32 "
        "{%0,%1,%2,%3}, {%4,%5,%6,%7}, {%8,%9}, {%0,%1,%2,%3};"
        : "+f"(c[0]), "+f"(c[1]), "+f"(c[2]), "+f"(c[3])
        : "r"(a[0]), "r"(a[1]), "r"(a[2]), "r"(a[3]), "r"(b0), "r"(b1));
}

__device__ __forceinline__ void cpa16(float* smem, const float* g) {
    uint32_t s = (uint32_t)__cvta_generic_to_shared(smem);
    asm volatile("cp.async.ca.shared.global [%0], [%1], 16;"
                 :: "r"(s), "l"(g));
}

// one-time tf32 truncation of W (288KB, L2-resident afterwards)
__global__ void k_wsplit(const float* __restrict__ w) {
    int i = blockIdx.x * blockDim.x + threadIdx.x;
    if (i < NF * FIN * FOUT) {
        uint32_t hu;
        asm("cvt.rna.tf32.f32 %0, %1;" : "=r"(hu) : "f"(w[i]));
        g_Wh[i] = __uint_as_float(hu);
    }
}

// ---------------------------------------------------------------------------
// T[n][f*96+c] = ds[f][n] * (x @ W_f)[n][c]
// 2-term TF32 GEMM: (Ah + Al) * Bh  (B truncated; residual ~2.8e-4 RMS)
// BM=128, BN=96 (blockIdx.y = filter), BK=32, 256 threads (8 warps, 4m x 2n)
// Output stored as fp16 into g_Th.
// ---------------------------------------------------------------------------
#define A_STR 36
#define B_STR 104
#define GEMM_SMEM ((128 * A_STR * 2 + 32 * B_STR) * 4)  // 50176 B

__global__ __launch_bounds__(256, 2) void k_gemm(const float* __restrict__ x,
                                                 const float* __restrict__ ds) {
    extern __shared__ float sm[];
    float* Ah = sm;
    float* Al = Ah + 128 * A_STR;
    float* Bh = Al + 128 * A_STR;

    const int m0 = blockIdx.x * 128;
    const int f  = blockIdx.y;
    const float* Wh = g_Wh + (size_t)f * FIN * FOUT;

    const int tid  = threadIdx.x;
    const int wid  = tid >> 5;
    const int lane = tid & 31;
    const int g    = lane >> 2;
    const int t4   = lane & 3;
    const int mw   = (wid & 3) * 32;
    const int nw   = (wid >> 2) * 48;

    int am[4], akq[4];
    bool aok[4];
    #pragma unroll
    for (int i = 0; i < 4; i++) {
        int idx = tid + i * 256;
        am[i]  = idx >> 3;
        akq[i] = (idx & 7) * 4;
        aok[i] = (m0 + am[i]) < NN;
    }
    int bk[3], bq[3];
    #pragma unroll
    for (int i = 0; i < 3; i++) {
        int idx = tid + i * 256;
        bk[i] = idx / 24;
        bq[i] = (idx - bk[i] * 24) * 4;
    }

    float c[2][6][4];
    #pragma unroll
    for (int mt = 0; mt < 2; mt++)
        #pragma unroll
        for (int nt = 0; nt < 6; nt++)
            #pragma unroll
            for (int q = 0; q < 4; q++) c[mt][nt][q] = 0.0f;

    float4 areg[4];
    #pragma unroll
    for (int i = 0; i < 4; i++)
        areg[i] = aok[i]
            ? *(const float4*)(x + (size_t)(m0 + am[i]) * FIN + akq[i])
            : make_float4(0.f, 0.f, 0.f, 0.f);

    for (int k0 = 0; k0 < FIN; k0 += 32) {
        #pragma unroll
        for (int i = 0; i < 3; i++)
            cpa16(Bh + bk[i] * B_STR + bq[i],
                  Wh + (size_t)(k0 + bk[i]) * FOUT + bq[i]);
        asm volatile("cp.async.commit_group;");

        #pragma unroll
        for (int i = 0; i < 4; i++) {
            float4 hv, lv;
            split4(areg[i], hv, lv);
            *(float4*)(Ah + am[i] * A_STR + akq[i]) = hv;
            *(float4*)(Al + am[i] * A_STR + akq[i]) = lv;
        }

        asm volatile("cp.async.wait_group 0;");
        __syncthreads();

        if (k0 + 32 < FIN) {
            #pragma unroll
            for (int i = 0; i < 4; i++)
                areg[i] = aok[i]
                    ? *(const float4*)(x + (size_t)(m0 + am[i]) * FIN + k0 + 32 + akq[i])
                    : make_float4(0.f, 0.f, 0.f, 0.f);
        }

        #pragma unroll
        for (int kk = 0; kk < 32; kk += 8) {
            uint32_t ah[2][4], al[2][4];
            #pragma unroll
            for (int mt = 0; mt < 2; mt++) {
                int mb = mw + mt * 16;
                ah[mt][0] = __float_as_uint(Ah[(mb + g)     * A_STR + kk + t4]);
                ah[mt][1] = __float_as_uint(Ah[(mb + g + 8) * A_STR + kk + t4]);
                ah[mt][2] = __float_as_uint(Ah[(mb + g)     * A_STR + kk + t4 + 4]);
                ah[mt][3] = __float_as_uint(Ah[(mb + g + 8) * A_STR + kk + t4 + 4]);
                al[mt][0] = __float_as_uint(Al[(mb + g)     * A_STR + kk + t4]);
                al[mt][1] = __float_as_uint(Al[(mb + g + 8) * A_STR + kk + t4]);
                al[mt][2] = __float_as_uint(Al[(mb + g)     * A_STR + kk + t4 + 4]);
                al[mt][3] = __float_as_uint(Al[(mb + g + 8) * A_STR + kk + t4 + 4]);
            }
            #pragma unroll
            for (int nt = 0; nt < 6; nt++) {
                int nb = nw + nt * 8 + g;
                uint32_t bh0 = __float_as_uint(Bh[(kk + t4)     * B_STR + nb]);
                uint32_t bh1 = __float_as_uint(Bh[(kk + t4 + 4) * B_STR + nb]);
                #pragma unroll
                for (int mt = 0; mt < 2; mt++) {
                    mma8(c[mt][nt], ah[mt], bh0, bh1);
                    mma8(c[mt][nt], al[mt], bh0, bh1);
                }
            }
        }
        __syncthreads();
    }

    // epilogue: scale by ds[f][row], convert to fp16, store to g_Th
    #pragma unroll
    for (int mt = 0; mt < 2; mt++) {
        int rbase = m0 + mw + mt * 16 + g;
        #pragma unroll
        for (int half = 0; half < 2; half++) {
            int r = rbase + half * 8;
            if (r < NN) {
                float s = ds[(size_t)f * NN + r];
                __half* dst = g_Th + (size_t)r * FT + f * FOUT + nw;
                #pragma unroll
                for (int nt = 0; nt < 6; nt++) {
                    __half2 p = __floats2half2_rn(s * c[mt][nt][half * 2 + 0],
                                                  s * c[mt][nt][half * 2 + 1]);
                    *(__half2*)(dst + nt * 8 + 2 * t4) = p;
                }
            }
        }
    }
}

// ---------------------------------------------------------------------------
// Fused SPMM + diag + relu + scale + bias + out.  One warp per row.
// Lane l (<24) owns cols [4l, 4l+4) of each filter; per edge it loads
// 3 x 8B (uint2 = 4 halves) from the gathered g_Th row.
// ---------------------------------------------------------------------------
__device__ __forceinline__ void fmah(float4& acc, float a, uint2 q) {
    float2 lo = __half22float2(*(const __half2*)&q.x);
    float2 hi = __half22float2(*(const __half2*)&q.y);
    acc.x = fmaf(a, lo.x, acc.x);
    acc.y = fmaf(a, lo.y, acc.y);
    acc.z = fmaf(a, hi.x, acc.z);
    acc.w = fmaf(a, hi.y, acc.w);
}

__device__ __forceinline__ float4 relu4(float4 v) {
    return make_float4(fmaxf(v.x, 0.f), fmaxf(v.y, 0.f),
                       fmaxf(v.z, 0.f), fmaxf(v.w, 0.f));
}

__device__ __forceinline__ float4 fma4(float a, float4 v, float4 c) {
    c.x = fmaf(a, v.x, c.x);
    c.y = fmaf(a, v.y, c.y);
    c.z = fmaf(a, v.z, c.z);
    c.w = fmaf(a, v.w, c.w);
    return c;
}

__global__ __launch_bounds__(256) void k_spmm(const float* __restrict__ ds,
                                              const float* __restrict__ bias,
                                              float* __restrict__ out) {
    int r = blockIdx.x * 8 + (threadIdx.x >> 5);
    int l = threadIdx.x & 31;
    if (r >= NN || l >= 24) return;

    int beg = g_start[r];
    int cnt = g_cnt[r];
    int end = beg + cnt;

    float4 a0 = make_float4(0.f, 0.f, 0.f, 0.f);
    float4 a1 = a0, a2 = a0;

    int e = beg;
    for (; e + 1 < end; e += 2) {
        int   c0 = g_csr_col[e],     c1 = g_csr_col[e + 1];
        float v0 = g_csr_val[e],     v1 = g_csr_val[e + 1];
        const uint2* p0 = (const uint2*)(g_Th + (size_t)c0 * FT);
        const uint2* p1 = (const uint2*)(g_Th + (size_t)c1 * FT);
        uint2 x0 = p0[l], x1 = p0[l + 24], x2 = p0[l + 48];
        uint2 y0 = p1[l], y1 = p1[l + 24], y2 = p1[l + 48];
        fmah(a0, v0, x0); fmah(a1, v0, x1); fmah(a2, v0, x2);
        fmah(a0, v1, y0); fmah(a1, v1, y1); fmah(a2, v1, y2);
    }
    if (e < end) {
        int   c0 = g_csr_col[e];
        float v0 = g_csr_val[e];
        const uint2* p0 = (const uint2*)(g_Th + (size_t)c0 * FT);
        fmah(a0, v0, p0[l]);
        fmah(a1, v0, p0[l + 24]);
        fmah(a2, v0, p0[l + 48]);
    }

    // diagonal term: sign_f * EPS/deg * T[r]  (deg = cnt + 1 self loop)
    float k = EPS / ((float)cnt + 1.0f);
    const uint2* pr = (const uint2*)(g_Th + (size_t)r * FT);
    fmah(a0, -k, pr[l]);
    fmah(a1,  k, pr[l + 24]);
    fmah(a2,  k, pr[l + 48]);

    float d0 = ds[r];
    float d1 = ds[NN + r];
    float d2 = ds[2 * NN + r];
    float4 o = ((const float4*)bias)[l];
    o = fma4(d0, relu4(a0), o);
    o = fma4(d1, relu4(a1), o);
    o = fma4(d2, relu4(a2), o);
    ((float4*)out)[(size_t)r * 24 + l] = o;
}

// ---------------------------------------------------------------------------
extern "C" void kernel_launch(void* const* d_in, const int* in_sizes, int n_in,
                              void* d_out, int out_size) {
    const float* x    = (const float*)d_in[0];  // [N, 256]
    const float* adj  = (const float*)d_in[1];  // [E]
    const float* ds   = (const float*)d_in[2];  // [3, N]
    const float* w    = (const float*)d_in[3];  // [3, 256, 96]
    const float* bias = (const float*)d_in[4];  // [96]
    const int*   ei   = (const int*)d_in[5];    // [2, E]
    float* out = (float*)d_out;                 // [N, 96]

    static cudaStream_t s2 = nullptr;
    static cudaEvent_t evFork = nullptr, evJoin = nullptr;
    if (!s2) {
        cudaStreamCreateWithFlags(&s2, cudaStreamNonBlocking);
        cudaEventCreateWithFlags(&evFork, cudaEventDisableTiming);
        cudaEventCreateWithFlags(&evJoin, cudaEventDisableTiming);
        cudaFuncSetAttribute(k_gemm, cudaFuncAttributeMaxDynamicSharedMemorySize,
                             GEMM_SMEM);
    }

    // fork: CSR build on s2, concurrent with wsplit+gemm on main stream
    cudaEventRecord(evFork, 0);
    cudaStreamWaitEvent(s2, evFork, 0);

    k_cnt0<<<(NN + 255) / 256, 256, 0, s2>>>();
    k_hist<<<(EE + 255) / 256, 256, 0, s2>>>(ei);
    k_scan1<<<NBLK, SCAN_B, 0, s2>>>();
    k_scan2<<<1, 1, 0, s2>>>();
    k_scan3<<<NBLK, SCAN_B, 0, s2>>>();
    k_scatter<<<(EE + 255) / 256, 256, 0, s2>>>(ei, adj);
    cudaEventRecord(evJoin, s2);

    k_wsplit<<<(NF * FIN * FOUT + 255) / 256, 256>>>(w);
    k_gemm<<<dim3((NN + 127) / 128, NF), 256, GEMM_SMEM>>>(x, ds);

    cudaStreamWaitEvent(0, evJoin, 0);
    k_spmm<<<(NN + 7) / 8, 256>>>(ds, bias, out);
}

// round 6
// speedup vs baseline: 4.7893x; 1.3425x over previous
#include <cuda_runtime.h>
#include <cuda_fp16.h>
#include <cstdint>

#define NN    50000
#define NNPAD 50048          // padded to grid multiple of 128 (pad rows stay 0)
#define EE    800000
#define FIN   256
#define FOUT  96
#define NF    3
#define FT    (NF * FOUT)    // 288
#define EPS   0.1f

#define SCAN_B 1024
#define NBLK   ((NN + SCAN_B - 1) / SCAN_B)   // 49

// Scratch (allocation-free rule: __device__ globals; zero-initialized once)
__device__ __align__(128) __half g_Th[(size_t)NN * FT];      // 28.8 MB
__device__ __align__(128) __half g_Xh[(size_t)NNPAD * FIN];  // 25.6 MB fp16 x
__device__ __align__(128) __half g_Wt[NF * FOUT * FIN];      // W^T fp16 [f][n][k]
__device__ int   g_cnt[NN];
__device__ int   g_start[NN];
__device__ int   g_cursor[NN];
__device__ int   g_part[NBLK];
__device__ __align__(16) int   g_csr_col[EE];
__device__ __align__(16) float g_csr_val[EE];

// ---------------------------------------------------------------------------
// CSR build (overlapped on side stream)
// ---------------------------------------------------------------------------
__global__ void k_cnt0() {
    int i = blockIdx.x * blockDim.x + threadIdx.x;
    if (i < NN) g_cnt[i] = 0;
}

__global__ void k_hist(const int* __restrict__ ei) {
    int e = blockIdx.x * blockDim.x + threadIdx.x;
    if (e < EE) atomicAdd(&g_cnt[ei[e]], 1);
}

__global__ __launch_bounds__(SCAN_B) void k_scan1() {
    __shared__ int s[SCAN_B];
    int i = blockIdx.x * SCAN_B + threadIdx.x;
    int v = (i < NN) ? g_cnt[i] : 0;
    s[threadIdx.x] = v;
    __syncthreads();
    #pragma unroll
    for (int off = 1; off < SCAN_B; off <<= 1) {
        int t = (threadIdx.x >= off) ? s[threadIdx.x - off] : 0;
        __syncthreads();
        s[threadIdx.x] += t;
        __syncthreads();
    }
    if (i < NN) g_start[i] = s[threadIdx.x] - v;
    if (threadIdx.x == SCAN_B - 1) g_part[blockIdx.x] = s[SCAN_B - 1];
}

__global__ void k_scan2() {
    __shared__ int s[64];
    int t = threadIdx.x;
    int v = (t < NBLK) ? g_part[t] : 0;
    s[t] = v;
    __syncthreads();
    #pragma unroll
    for (int off = 1; off < 64; off <<= 1) {
        int u = (t >= off) ? s[t - off] : 0;
        __syncthreads();
        s[t] += u;
        __syncthreads();
    }
    if (t < NBLK) g_part[t] = s[t] - v;   // exclusive
}

__global__ __launch_bounds__(SCAN_B) void k_scan3() {
    int i = blockIdx.x * SCAN_B + threadIdx.x;
    if (i < NN) {
        int s = g_start[i] + g_part[blockIdx.x];
        g_start[i]  = s;
        g_cursor[i] = s;
    }
}

__global__ void k_scatter(const int* __restrict__ ei,
                          const float* __restrict__ adj) {
    int e = blockIdx.x * blockDim.x + threadIdx.x;
    if (e < EE) {
        int r = ei[e];
        int pos = atomicAdd(&g_cursor[r], 1);
        g_csr_col[pos] = ei[EE + e];
        g_csr_val[pos] = adj[e];
    }
}

// ---------------------------------------------------------------------------
// One-time conversions: W -> fp16 transposed [f][n][k]; x -> fp16
// ---------------------------------------------------------------------------
__global__ void k_wcvt(const float* __restrict__ w) {
    int i = blockIdx.x * blockDim.x + threadIdx.x;   // over NF*FIN*FOUT
    if (i < NF * FIN * FOUT) {
        int f = i / (FIN * FOUT);
        int rem = i - f * FIN * FOUT;
        int k = rem / FOUT;
        int n = rem - k * FOUT;
        g_Wt[(size_t)f * FOUT * FIN + (size_t)n * FIN + k] = __float2half(w[i]);
    }
}

__global__ void k_xcvt(const float* __restrict__ x) {
    int i = blockIdx.x * blockDim.x + threadIdx.x;   // over NN*FIN/4
    if (i < NN * FIN / 4) {
        float4 v = ((const float4*)x)[i];
        __half2 lo = __floats2half2_rn(v.x, v.y);
        __half2 hi = __floats2half2_rn(v.z, v.w);
        uint2 p;
        p.x = *(uint32_t*)&lo;
        p.y = *(uint32_t*)&hi;
        ((uint2*)g_Xh)[i] = p;
    }
}

// ---------------------------------------------------------------------------
// fp16 GEMM: T[n][f*96+c] = ds[f][n] * (x @ W_f)[n][c]
// BM=128, BN=96 (blockIdx.y = filter), BK=64, 256 threads (8 warps, 4m x 2n).
// Pure cp.async double-buffered mainloop; mma.m16n8k16.f16.
// Smem strides 72 halves -> conflict-free half2 fragment loads.
// ---------------------------------------------------------------------------
#define A_STR 72
#define B_STR 72
#define STAGE_H (128 * A_STR + 96 * B_STR)          // halves per stage = 16128
#define GEMM_SMEM (2 * STAGE_H * 2)                 // bytes = 64512
#define NIT (FIN / 64)                              // 4

__device__ __forceinline__ void cpa16h(__half* smem, const __half* g) {
    uint32_t s = (uint32_t)__cvta_generic_to_shared(smem);
    asm volatile("cp.async.ca.shared.global [%0], [%1], 16;"
                 :: "r"(s), "l"(g));
}

__device__ __forceinline__ void mma16(float* c, const uint32_t* a,
                                      uint32_t b0, uint32_t b1) {
    asm volatile(
        "mma.sync.aligned.m16n8k16.row.col.f32.f16.f16.f32 "
        "{%0,%1,%2,%3}, {%4,%5,%6,%7}, {%8,%9}, {%0,%1,%2,%3};"
        : "+f"(c[0]), "+f"(c[1]), "+f"(c[2]), "+f"(c[3])
        : "r"(a[0]), "r"(a[1]), "r"(a[2]), "r"(a[3]), "r"(b0), "r"(b1));
}

__global__ __launch_bounds__(256, 2) void k_gemm(const float* __restrict__ ds) {
    extern __shared__ __half sm[];

    const int m0 = blockIdx.x * 128;
    const int f  = blockIdx.y;
    const __half* Wt = g_Wt + (size_t)f * FOUT * FIN;
    const __half* Xb = g_Xh + (size_t)m0 * FIN;

    const int tid  = threadIdx.x;
    const int wid  = tid >> 5;
    const int lane = tid & 31;
    const int g    = lane >> 2;
    const int t4   = lane & 3;
    const int mw   = (wid & 3) * 32;
    const int nw   = (wid >> 2) * 48;

    float c[2][6][4];
    #pragma unroll
    for (int mt = 0; mt < 2; mt++)
        #pragma unroll
        for (int nt = 0; nt < 6; nt++)
            #pragma unroll
            for (int q = 0; q < 4; q++) c[mt][nt][q] = 0.0f;

    // fetch stage s (k0 = s*64) into buffer (s & 1)
    auto fetch = [&](int s) {
        __half* As = sm + (s & 1) * STAGE_H;
        __half* Bs = As + 128 * A_STR;
        int k0 = s * 64;
        // A: 128 rows x 8 kgroups of 8 halves = 1024 tasks, 4/thread
        #pragma unroll
        for (int i = 0; i < 4; i++) {
            int task = tid + i * 256;
            int m  = task >> 3;
            int kg = (task & 7) * 8;
            cpa16h(As + m * A_STR + kg, Xb + (size_t)m * FIN + k0 + kg);
        }
        // B: 96 rows x 8 kgroups = 768 tasks, 3/thread
        #pragma unroll
        for (int i = 0; i < 3; i++) {
            int task = tid + i * 256;
            int n  = task >> 3;
            int kg = (task & 7) * 8;
            cpa16h(Bs + n * B_STR + kg, Wt + (size_t)n * FIN + k0 + kg);
        }
        asm volatile("cp.async.commit_group;");
    };

    fetch(0);
    fetch(1);

    for (int it = 0; it < NIT; it++) {
        asm volatile("cp.async.wait_group 1;");
        __syncthreads();

        const __half* As = sm + (it & 1) * STAGE_H;
        const __half* Bs = As + 128 * A_STR;

        #pragma unroll
        for (int kk = 0; kk < 64; kk += 16) {
            uint32_t a[2][4];
            #pragma unroll
            for (int mt = 0; mt < 2; mt++) {
                int mb = mw + mt * 16;
                a[mt][0] = *(const uint32_t*)(As + (mb + g)     * A_STR + kk + 2 * t4);
                a[mt][1] = *(const uint32_t*)(As + (mb + g + 8) * A_STR + kk + 2 * t4);
                a[mt][2] = *(const uint32_t*)(As + (mb + g)     * A_STR + kk + 2 * t4 + 8);
                a[mt][3] = *(const uint32_t*)(As + (mb + g + 8) * A_STR + kk + 2 * t4 + 8);
            }
            #pragma unroll
            for (int nt = 0; nt < 6; nt++) {
                int nb = nw + nt * 8 + g;
                uint32_t b0 = *(const uint32_t*)(Bs + nb * B_STR + kk + 2 * t4);
                uint32_t b1 = *(const uint32_t*)(Bs + nb * B_STR + kk + 2 * t4 + 8);
                mma16(c[0][nt], a[0], b0, b1);
                mma16(c[1][nt], a[1], b0, b1);
            }
        }
        __syncthreads();
        if (it + 2 < NIT) fetch(it + 2);
        else asm volatile("cp.async.commit_group;");
    }

    // epilogue: scale by ds[f][row], convert to fp16, store to g_Th
    #pragma unroll
    for (int mt = 0; mt < 2; mt++) {
        int rbase = m0 + mw + mt * 16 + g;
        #pragma unroll
        for (int half = 0; half < 2; half++) {
            int r = rbase + half * 8;
            if (r < NN) {
                float s = ds[(size_t)f * NN + r];
                __half* dst = g_Th + (size_t)r * FT + f * FOUT + nw;
                #pragma unroll
                for (int nt = 0; nt < 6; nt++) {
                    __half2 p = __floats2half2_rn(s * c[mt][nt][half * 2 + 0],
                                                  s * c[mt][nt][half * 2 + 1]);
                    *(__half2*)(dst + nt * 8 + 2 * t4) = p;
                }
            }
        }
    }
}

// ---------------------------------------------------------------------------
// Fused SPMM + diag + relu + scale + bias + out.  One warp per row.
// ---------------------------------------------------------------------------
__device__ __forceinline__ void fmah(float4& acc, float a, uint2 q) {
    float2 lo = __half22float2(*(const __half2*)&q.x);
    float2 hi = __half22float2(*(const __half2*)&q.y);
    acc.x = fmaf(a, lo.x, acc.x);
    acc.y = fmaf(a, lo.y, acc.y);
    acc.z = fmaf(a, hi.x, acc.z);
    acc.w = fmaf(a, hi.y, acc.w);
}

__device__ __forceinline__ float4 relu4(float4 v) {
    return make_float4(fmaxf(v.x, 0.f), fmaxf(v.y, 0.f),
                       fmaxf(v.z, 0.f), fmaxf(v.w, 0.f));
}

__device__ __forceinline__ float4 fma4(float a, float4 v, float4 c) {
    c.x = fmaf(a, v.x, c.x);
    c.y = fmaf(a, v.y, c.y);
    c.z = fmaf(a, v.z, c.z);
    c.w = fmaf(a, v.w, c.w);
    return c;
}

__global__ __launch_bounds__(256) void k_spmm(const float* __restrict__ ds,
                                              const float* __restrict__ bias,
                                              float* __restrict__ out) {
    int r = blockIdx.x * 8 + (threadIdx.x >> 5);
    int l = threadIdx.x & 31;
    if (r >= NN || l >= 24) return;

    int beg = g_start[r];
    int cnt = g_cnt[r];
    int end = beg + cnt;

    float4 a0 = make_float4(0.f, 0.f, 0.f, 0.f);
    float4 a1 = a0, a2 = a0;

    int e = beg;
    for (; e + 1 < end; e += 2) {
        int   c0 = g_csr_col[e],     c1 = g_csr_col[e + 1];
        float v0 = g_csr_val[e],     v1 = g_csr_val[e + 1];
        const uint2* p0 = (const uint2*)(g_Th + (size_t)c0 * FT);
        const uint2* p1 = (const uint2*)(g_Th + (size_t)c1 * FT);
        uint2 x0 = p0[l], x1 = p0[l + 24], x2 = p0[l + 48];
        uint2 y0 = p1[l], y1 = p1[l + 24], y2 = p1[l + 48];
        fmah(a0, v0, x0); fmah(a1, v0, x1); fmah(a2, v0, x2);
        fmah(a0, v1, y0); fmah(a1, v1, y1); fmah(a2, v1, y2);
    }
    if (e < end) {
        int   c0 = g_csr_col[e];
        float v0 = g_csr_val[e];
        const uint2* p0 = (const uint2*)(g_Th + (size_t)c0 * FT);
        fmah(a0, v0, p0[l]);
        fmah(a1, v0, p0[l + 24]);
        fmah(a2, v0, p0[l + 48]);
    }

    // diagonal term: sign_f * EPS/deg * T[r]  (deg = cnt + 1 self loop)
    float k = EPS / ((float)cnt + 1.0f);
    const uint2* pr = (const uint2*)(g_Th + (size_t)r * FT);
    fmah(a0, -k, pr[l]);
    fmah(a1,  k, pr[l + 24]);
    fmah(a2,  k, pr[l + 48]);

    float d0 = ds[r];
    float d1 = ds[NN + r];
    float d2 = ds[2 * NN + r];
    float4 o = ((const float4*)bias)[l];
    o = fma4(d0, relu4(a0), o);
    o = fma4(d1, relu4(a1), o);
    o = fma4(d2, relu4(a2), o);
    ((float4*)out)[(size_t)r * 24 + l] = o;
}

// ---------------------------------------------------------------------------
extern "C" void kernel_launch(void* const* d_in, const int* in_sizes, int n_in,
                              void* d_out, int out_size) {
    const float* x    = (const float*)d_in[0];  // [N, 256]
    const float* adj  = (const float*)d_in[1];  // [E]
    const float* ds   = (const float*)d_in[2];  // [3, N]
    const float* w    = (const float*)d_in[3];  // [3, 256, 96]
    const float* bias = (const float*)d_in[4];  // [96]
    const int*   ei   = (const int*)d_in[5];    // [2, E]
    float* out = (float*)d_out;                 // [N, 96]

    static cudaStream_t s2 = nullptr;
    static cudaEvent_t evFork = nullptr, evJoin = nullptr;
    if (!s2) {
        cudaStreamCreateWithFlags(&s2, cudaStreamNonBlocking);
        cudaEventCreateWithFlags(&evFork, cudaEventDisableTiming);
        cudaEventCreateWithFlags(&evJoin, cudaEventDisableTiming);
        cudaFuncSetAttribute(k_gemm, cudaFuncAttributeMaxDynamicSharedMemorySize,
                             GEMM_SMEM);
    }

    // fork: CSR build on s2, concurrent with cvt+gemm on main stream
    cudaEventRecord(evFork, 0);
    cudaStreamWaitEvent(s2, evFork, 0);

    k_cnt0<<<(NN + 255) / 256, 256, 0, s2>>>();
    k_hist<<<(EE + 255) / 256, 256, 0, s2>>>(ei);
    k_scan1<<<NBLK, SCAN_B, 0, s2>>>();
    k_scan2<<<1, 64, 0, s2>>>();
    k_scan3<<<NBLK, SCAN_B, 0, s2>>>();
    k_scatter<<<(EE + 255) / 256, 256, 0, s2>>>(ei, adj);
    cudaEventRecord(evJoin, s2);

    k_wcvt<<<(NF * FIN * FOUT + 255) / 256, 256>>>(w);
    k_xcvt<<<(NN * FIN / 4 + 255) / 256, 256>>>(x);
    k_gemm<<<dim3((NN + 127) / 128, NF), 256, GEMM_SMEM>>>(ds);

    cudaStreamWaitEvent(0, evJoin, 0);
    k_spmm<<<(NN + 7) / 8, 256>>>(ds, bias, out);
}